// round 9
// baseline (speedup 1.0000x reference)
#include <cuda_runtime.h>
#include <math.h>
#include <stdint.h>

#define BB 2
#define SS 2048
#define DD 1024
#define NHH 16
#define HDD 64
#define FFF 4096
#define RR (BB*SS)   // 4096 rows
#define D3 (3*DD)    // merged qkv width

// ---------------- scratch ---------------------------------------------------------
__device__ float g_h  [RR*DD];                      // LN1 out / LN2 out
__device__ float g_qkv[(size_t)RR*D3];              // Q|K|V   / x2 (reused)
__device__ float g_ao [RR*DD];                      // attn output (b,s,(h,d))
__device__ float g_ff [(size_t)RR*FFF];             // FFN hidden
__device__ float g_P  [(size_t)BB*NHH*SS*SS];       // unnormalized exp(scores) (b,h,n,m)
__device__ float g_rs [(size_t)BB*NHH*SS];          // softmax row sums
__device__ float g_wr [12*1024*1024];               // tf32-rounded weights

// ---------------- helpers ---------------------------------------------------------
__device__ __forceinline__ void cpa16(void* dst, const void* src) {
    uint32_t d = (uint32_t)__cvta_generic_to_shared(dst);
    asm volatile("cp.async.ca.shared.global [%0], [%1], 16;" :: "r"(d), "l"(src));
}
__device__ __forceinline__ void cp_commit() { asm volatile("cp.async.commit_group;"); }
template<int N> __device__ __forceinline__ void cp_wait() {
    asm volatile("cp.async.wait_group %0;" :: "n"(N));
}
__device__ __forceinline__ float f2tf(float x) {
    uint32_t r;
    asm("cvt.rna.tf32.f32 %0, %1;" : "=r"(r) : "f"(x));
    return __uint_as_float(r);
}
__device__ __forceinline__ void mma8(float* c, const uint32_t* a, const uint32_t* b) {
    asm volatile(
        "mma.sync.aligned.m16n8k8.row.col.f32.tf32.tf32.f32 "
        "{%0,%1,%2,%3},{%4,%5,%6,%7},{%8,%9},{%0,%1,%2,%3};"
        : "+f"(c[0]), "+f"(c[1]), "+f"(c[2]), "+f"(c[3])
        : "r"(a[0]), "r"(a[1]), "r"(a[2]), "r"(a[3]), "r"(b[0]), "r"(b[1]));
}
__device__ __forceinline__ void ldsm4(uint32_t* r, uint32_t a) {
    asm volatile("ldmatrix.sync.aligned.m8n8.x4.shared.b16 {%0,%1,%2,%3}, [%4];"
        : "=r"(r[0]), "=r"(r[1]), "=r"(r[2]), "=r"(r[3]) : "r"(a));
}

// ---------------- prep: round weights, merge wq|wkv -------------------------------
__global__ void __launch_bounds__(256)
round4_kernel(const float* __restrict__ in, float* __restrict__ out, int n4)
{
    int i = blockIdx.x * 256 + threadIdx.x;
    if (i < n4) {
        float4 v = ((const float4*)in)[i];
        v.x = f2tf(v.x); v.y = f2tf(v.y); v.z = f2tf(v.z); v.w = f2tf(v.w);
        ((float4*)out)[i] = v;
    }
}
// merged qkv weights: out[r][0:1024]=wq[r], out[r][1024:3072]=wkv[r]  (rounded)
__global__ void __launch_bounds__(256)
merge_qkv_kernel(const float* __restrict__ wq, const float* __restrict__ wkv,
                 float* __restrict__ out)
{
    int i = blockIdx.x * 256 + threadIdx.x;      // over 1024*768 float4s
    int row = i / 768, c4 = i % 768;
    float4 v;
    if (c4 < 256) v = ((const float4*)wq)[row*256 + c4];
    else          v = ((const float4*)wkv)[row*512 + (c4 - 256)];
    v.x = f2tf(v.x); v.y = f2tf(v.y); v.z = f2tf(v.z); v.w = f2tf(v.w);
    ((float4*)out)[i] = v;
}

// ---------------- dense tf32 GEMM: 128x128, BK=32, 3-stage, ldmatrix A ------------
#define GSTG 8960              // u32 per stage (4608 A + 4352 B)
#define GSMEM_BYTES (3*GSTG*4)
template<int MODE, bool ROUND>
__global__ void __launch_bounds__(256, 2)
mma_gemm(const float* __restrict__ A, int lda,
         const float* __restrict__ B, int ldb,
         float* __restrict__ C, int ldc, int K,
         const float* __restrict__ bias,
         const float* __restrict__ res, int ldr)
{
    extern __shared__ uint32_t smu[];
    float* smf = (float*)smu;

    int tid = threadIdx.x, lane = tid & 31, w = tid >> 5;
    int wm = (w & 1) * 64, wn = (w >> 1) * 32;
    int row0 = blockIdx.y * 128, col0 = blockIdx.x * 128;

    int i8 = lane & 7, j8 = lane >> 3;
    uint32_t abase = (uint32_t)__cvta_generic_to_shared(smu);
    uint32_t aoff[4];
#pragma unroll
    for (int mi = 0; mi < 4; mi++)
        aoff[mi] = ((wm + mi*16 + i8 + (j8 & 1)*8)*36 + (j8 >> 1)*4) * 4;

    float acc[4][4][4];
#pragma unroll
    for (int i = 0; i < 4; i++)
#pragma unroll
        for (int j = 0; j < 4; j++)
#pragma unroll
            for (int l = 0; l < 4; l++) acc[i][j][l] = 0.f;

    int niter = K / 32;

    auto load_blk = [&](int s, int k0) {
        float* As = smf + s*GSTG;
        float* Bs = smf + s*GSTG + 4608;
#pragma unroll
        for (int i = 0; i < 4; i++) {
            int idx = tid + i*256;
            int m = idx >> 3, k4 = (idx & 7) * 4;
            cpa16(&As[m*36 + k4], A + (size_t)(row0 + m)*lda + k0 + k4);
        }
#pragma unroll
        for (int i = 0; i < 4; i++) {
            int idx = tid + i*256;
            int k = idx >> 5, c4 = (idx & 31) * 4;
            cpa16(&Bs[k*136 + c4], B + (size_t)(k0 + k)*ldb + col0 + c4);
        }
        cp_commit();
    };

    load_blk(0, 0);
    load_blk(1, 32);

    for (int it = 0; it < niter; it++) {
        cp_wait<1>();
        __syncthreads();
        if (it + 2 < niter) load_blk((it + 2) % 3, (it + 2) * 32);

        int s = it % 3;
        const uint32_t* Bb = smu + s*GSTG + 4608;
        uint32_t as_base = abase + s*GSTG*4;
#pragma unroll
        for (int ks = 0; ks < 32; ks += 8) {
            uint32_t af[4][4], bf[4][2];
#pragma unroll
            for (int mi = 0; mi < 4; mi++)
                ldsm4(af[mi], as_base + aoff[mi] + ks*4);
#pragma unroll
            for (int ni = 0; ni < 4; ni++) {
                int n = wn + ni*8 + (lane >> 2), kb = ks + (lane & 3);
                bf[ni][0] = Bb[kb*136 + n];  bf[ni][1] = Bb[(kb+4)*136 + n];
            }
#pragma unroll
            for (int mi = 0; mi < 4; mi++)
#pragma unroll
                for (int ni = 0; ni < 4; ni++)
                    mma8(acc[mi][ni], af[mi], bf[ni]);
        }
    }

#pragma unroll
    for (int mi = 0; mi < 4; mi++) {
#pragma unroll
        for (int ni = 0; ni < 4; ni++) {
            int r = row0 + wm + mi*16 + (lane >> 2);
            int c = col0 + wn + ni*8 + 2*(lane & 3);
#pragma unroll
            for (int half = 0; half < 2; half++) {
                int rr = r + half*8;
                float v0 = acc[mi][ni][half*2 + 0];
                float v1 = acc[mi][ni][half*2 + 1];
                if (MODE == 1) {
                    v0 += bias[c]   + res[(size_t)rr*ldr + c];
                    v1 += bias[c+1] + res[(size_t)rr*ldr + c + 1];
                } else if (MODE == 2) {
                    v0 = fmaxf(v0 + bias[c], 0.f);
                    v1 = fmaxf(v1 + bias[c+1], 0.f);
                }
                if (ROUND) { v0 = f2tf(v0); v1 = f2tf(v1); }
                *(float2*)(C + (size_t)rr*ldc + c) = make_float2(v0, v1);
            }
        }
    }
}

// ---------------- fused attention: reads merged qkv (row stride 3072) -------------
// grid (S/64, B*NH), 512 thr. 32 iters of 64 keys, K/V double buffered.
__global__ void __launch_bounds__(512, 2)
fused_attn(const float* __restrict__ QKV,
           float* __restrict__ Eout, float* __restrict__ rs_g,
           float* __restrict__ Og)
{
    extern __shared__ float sm[];
    float* Qs = sm;                    // [64][68]
    float* Ks = Qs + 64*68;            // [2][64][68]
    float* Vs = Ks + 2*64*68;          // [2][64][72]
    float* Es = Vs + 2*64*72;          // [64][68]
    float* rs = Es + 64*68;            // [64]

    int bh = blockIdx.y, b = bh >> 4, h = bh & 15;
    int n0 = blockIdx.x * 64;
    const float* Qp = QKV + (size_t)b*SS*D3 + h*64;          // cols [0,1024)
    const float* Kp = QKV + (size_t)b*SS*D3 + DD   + h*64;   // cols [1024,2048)
    const float* Vp = QKV + (size_t)b*SS*D3 + 2*DD + h*64;   // cols [2048,3072)
    float* Ep = Eout + (size_t)bh*SS*SS + (size_t)n0*SS;

    int tid = threadIdx.x, lane = tid & 31, w = tid >> 5;
    int wy = w & 1, wx = w >> 1;       // wy: 32-row half of 64; wx: 8-col group of 64

    int i8 = lane & 7, j8 = lane >> 3;
    uint32_t qbase = (uint32_t)__cvta_generic_to_shared(Qs);
    uint32_t ebase = (uint32_t)__cvta_generic_to_shared(Es);
    uint32_t moff[2];
#pragma unroll
    for (int mi = 0; mi < 2; mi++)
        moff[mi] = ((wy*32 + mi*16 + i8 + (j8 & 1)*8)*68 + (j8 >> 1)*4) * 4;

    if (tid < 64) rs[tid] = 0.f;

#pragma unroll
    for (int i = 0; i < 2; i++) {
        int idx = tid + i*512; int r = idx >> 4, c4 = (idx & 15) * 4;
        cpa16(&Qs[r*68 + c4], Qp + (size_t)(n0 + r)*D3 + c4);
        cpa16(&Ks[r*68 + c4], Kp + (size_t)r*D3 + c4);
        cpa16(&Vs[r*72 + c4], Vp + (size_t)r*D3 + c4);
    }
    cp_commit();
#pragma unroll
    for (int i = 0; i < 2; i++) {
        int idx = tid + i*512; int r = idx >> 4, c4 = (idx & 15) * 4;
        cpa16(&Ks[64*68 + r*68 + c4], Kp + (size_t)(64 + r)*D3 + c4);
        cpa16(&Vs[64*72 + r*72 + c4], Vp + (size_t)(64 + r)*D3 + c4);
    }
    cp_commit();

    float acc_o[2][4];
    float psum[2][2];
#pragma unroll
    for (int i = 0; i < 2; i++) {
        psum[i][0] = psum[i][1] = 0.f;
#pragma unroll
        for (int l = 0; l < 4; l++) acc_o[i][l] = 0.f;
    }

    for (int it = 0; it < 32; it++) {
        int buf = it & 1;
        int m0 = it * 64;
        if (it + 1 < 32) cp_wait<1>(); else cp_wait<0>();
        __syncthreads();
        const uint32_t* Kb = (const uint32_t*)(Ks + buf*64*68);
        const uint32_t* Vb = (const uint32_t*)(Vs + buf*64*72);

        // ---- S = Q K^T : 64(n) x 64(m), k=64 ----
        float acc_s[2][4];
#pragma unroll
        for (int i = 0; i < 2; i++)
#pragma unroll
            for (int l = 0; l < 4; l++) acc_s[i][l] = 0.f;
#pragma unroll
        for (int ks = 0; ks < 64; ks += 8) {
            uint32_t af[2][4], bf[2];
            ldsm4(af[0], qbase + moff[0] + ks*4);
            ldsm4(af[1], qbase + moff[1] + ks*4);
            {
                int m = wx*8 + (lane >> 2), kk = ks + (lane & 3);
                bf[0] = Kb[m*68 + kk];  bf[1] = Kb[m*68 + kk + 4];
            }
            mma8(acc_s[0], af[0], bf);
            mma8(acc_s[1], af[1], bf);
        }

        // ---- E = round(exp(S/8)); per-thread rowsum; store to Es ----
#pragma unroll
        for (int mi = 0; mi < 2; mi++) {
            int r = wy*32 + mi*16 + (lane >> 2);
            int m = wx*8 + 2*(lane & 3);
            float e0 = f2tf(__expf(acc_s[mi][0] * 0.125f));
            float e1 = f2tf(__expf(acc_s[mi][1] * 0.125f));
            float e2 = f2tf(__expf(acc_s[mi][2] * 0.125f));
            float e3 = f2tf(__expf(acc_s[mi][3] * 0.125f));
            *(float2*)&Es[r*68 + m]     = make_float2(e0, e1);
            *(float2*)&Es[(r+8)*68 + m] = make_float2(e2, e3);
            psum[mi][0] += e0 + e1;
            psum[mi][1] += e2 + e3;
        }
        __syncthreads();

        // ---- coalesced E tile write (64 x 64) ----
        {
            int r = tid >> 3, q = (tid & 7) * 2;
            const float4* src = (const float4*)&Es[r*68];
            float4* dst = (float4*)(Ep + (size_t)r*SS + m0);
            dst[q] = src[q]; dst[q + 1] = src[q + 1];
        }

        // ---- O += E V : 64(n) x 64(d), k=64 ----
#pragma unroll
        for (int ks = 0; ks < 64; ks += 8) {
            uint32_t af[2][4], bf[2];
            ldsm4(af[0], ebase + moff[0] + ks*4);
            ldsm4(af[1], ebase + moff[1] + ks*4);
            {
                int d = wx*8 + (lane >> 2), kk = ks + (lane & 3);
                bf[0] = Vb[kk*72 + d];  bf[1] = Vb[(kk+4)*72 + d];
            }
            mma8(acc_o[0], af[0], bf);
            mma8(acc_o[1], af[1], bf);
        }
        __syncthreads();

        // ---- prefetch K/V tile it+2 into buf ----
        if (it + 2 < 32) {
            int mn = (it + 2) * 64;
#pragma unroll
            for (int i = 0; i < 2; i++) {
                int idx = tid + i*512; int r = idx >> 4, c4 = (idx & 15) * 4;
                cpa16(&Ks[buf*64*68 + r*68 + c4], Kp + (size_t)(mn + r)*D3 + c4);
                cpa16(&Vs[buf*64*72 + r*72 + c4], Vp + (size_t)(mn + r)*D3 + c4);
            }
            cp_commit();
        }
    }

    // ---- rowsum reduction (once) ----
#pragma unroll
    for (int mi = 0; mi < 2; mi++) {
        int r = wy*32 + mi*16 + (lane >> 2);
        float p0 = psum[mi][0], p1 = psum[mi][1];
        p0 += __shfl_xor_sync(0xffffffffu, p0, 1);
        p0 += __shfl_xor_sync(0xffffffffu, p0, 2);
        p1 += __shfl_xor_sync(0xffffffffu, p1, 1);
        p1 += __shfl_xor_sync(0xffffffffu, p1, 2);
        if ((lane & 3) == 0) { atomicAdd(&rs[r], p0); atomicAdd(&rs[r+8], p1); }
    }
    __syncthreads();

    if (tid < 64) rs_g[(size_t)bh*SS + n0 + tid] = rs[tid];
    float* Op = Og + (size_t)b*SS*DD + h*64;
#pragma unroll
    for (int mi = 0; mi < 2; mi++) {
        int r = wy*32 + mi*16 + (lane >> 2);
        int d = wx*8 + 2*(lane & 3);
        float inv0 = 1.f / rs[r], inv1 = 1.f / rs[r+8];
        *(float2*)(Op + (size_t)(n0 + r)*DD + d) =
            make_float2(f2tf(acc_o[mi][0]*inv0), f2tf(acc_o[mi][1]*inv0));
        *(float2*)(Op + (size_t)(n0 + r + 8)*DD + d) =
            make_float2(f2tf(acc_o[mi][2]*inv1), f2tf(acc_o[mi][3]*inv1));
    }
}

// ---------------- LayerNorm (tf32-rounded output) ---------------------------------
__global__ void __launch_bounds__(256)
ln_kernel(const float* __restrict__ x, const float* __restrict__ g,
          const float* __restrict__ beta, float* __restrict__ out)
{
    __shared__ float red[64];
    int row = blockIdx.x;
    const float* xr = x + (size_t)row*DD;
    float* orow = out + (size_t)row*DD;
    int t = threadIdx.x;
    float v[4]; float s = 0.f, sq = 0.f;
#pragma unroll
    for (int i = 0; i < 4; i++) {
        v[i] = xr[t + i*256];
        s += v[i];
        sq = fmaf(v[i], v[i], sq);
    }
#pragma unroll
    for (int o = 16; o > 0; o >>= 1) {
        s  += __shfl_down_sync(0xffffffffu, s,  o);
        sq += __shfl_down_sync(0xffffffffu, sq, o);
    }
    int lane = t & 31, w = t >> 5;
    if (lane == 0) { red[w] = s; red[w + 32] = sq; }
    __syncthreads();
    if (t == 0) {
        float ts = 0.f, tq = 0.f;
        for (int i = 0; i < 8; i++) { ts += red[i]; tq += red[i + 32]; }
        float mu  = ts * (1.0f / DD);
        float var = tq * (1.0f / DD) - mu * mu;
        red[0] = mu;
        red[1] = rsqrtf(var + 1e-5f);
    }
    __syncthreads();
    float mu = red[0], r = red[1];
#pragma unroll
    for (int i = 0; i < 4; i++) {
        int c = t + i*256;
        orow[c] = f2tf((v[i] - mu) * r * g[c] + beta[c]);
    }
}

// ---------------- Transpose+normalize: E(b,h,n,m)/rowsum -> attn(b,n,m,h) --------
__global__ void __launch_bounds__(256)
attn_transpose(const float* __restrict__ P, const float* __restrict__ rs_g,
               float* __restrict__ outA)
{
    __shared__ float tbuf[16][130];
    __shared__ float invs[16];
    int m0 = blockIdx.x * 128;
    int n  = blockIdx.y;
    int b  = blockIdx.z;
    int t  = threadIdx.x;
    if (t < 16) invs[t] = 1.f / rs_g[((size_t)(b*NHH + t))*SS + n];
#pragma unroll
    for (int i = 0; i < 8; i++) {
        int idx = t + i*256;
        int h = idx >> 7, m = idx & 127;
        tbuf[h][m] = P[(((size_t)(b*NHH + h))*SS + n)*SS + m0 + m];
    }
    __syncthreads();
    float* op = outA + (((size_t)b*SS + n)*SS + m0) * NHH;
#pragma unroll
    for (int i = 0; i < 8; i++) {
        int idx = t + i*256;          // idx = m*16 + h
        int m = idx >> 4, h = idx & 15;
        op[idx] = tbuf[h][m] * invs[h];
    }
}

// ---------------- launcher -------------------------------------------------------
extern "C" void kernel_launch(void* const* d_in, const int* in_sizes, int n_in,
                              void* d_out, int out_size)
{
    const float* x    = (const float*)d_in[0];
    const float* ln1g = (const float*)d_in[1];
    const float* ln1b = (const float*)d_in[2];
    const float* wq   = (const float*)d_in[3];
    const float* wkv  = (const float*)d_in[4];
    const float* wo   = (const float*)d_in[5];
    const float* bo   = (const float*)d_in[6];
    const float* ln2g = (const float*)d_in[7];
    const float* ln2b = (const float*)d_in[8];
    const float* w1   = (const float*)d_in[9];
    const float* b1   = (const float*)d_in[10];
    const float* w2   = (const float*)d_in[11];
    const float* b2   = (const float*)d_in[12];

    float* out = (float*)d_out;
    size_t attn_elems = (size_t)BB * SS * SS * NHH;
    float* out_attn = out + ((size_t)out_size - attn_elems);

    float *hp, *qkvp, *aop, *ffp, *Pp, *rsp, *wrp;
    cudaGetSymbolAddress((void**)&hp,   g_h);
    cudaGetSymbolAddress((void**)&qkvp, g_qkv);
    cudaGetSymbolAddress((void**)&aop,  g_ao);
    cudaGetSymbolAddress((void**)&ffp,  g_ff);
    cudaGetSymbolAddress((void**)&Pp,   g_P);
    cudaGetSymbolAddress((void**)&rsp,  g_rs);
    cudaGetSymbolAddress((void**)&wrp,  g_wr);
    float* x2p = qkvp;  // reuse: qkv dead after fused_attn
    float* h2p = hp;    // reuse: LN1 out dead after qkv gemm

    float* wqkv_r = wrp;                 // 3M floats [1024][3072]
    float* wo_r   = wrp + 3*1024*1024;   // 1M
    float* w1_r   = wrp + 4*1024*1024;   // 4M
    float* w2_r   = wrp + 8*1024*1024;   // 4M

    int attn_smem = (64*68 + 2*64*68 + 2*64*72 + 64*68 + 64) * 4;   // 106752 B
    cudaFuncSetAttribute(fused_attn, cudaFuncAttributeMaxDynamicSharedMemorySize,
                         attn_smem);
    cudaFuncSetAttribute(fused_attn, cudaFuncAttributePreferredSharedMemoryCarveout, 100);
    cudaFuncSetAttribute(mma_gemm<0, true>,
                         cudaFuncAttributeMaxDynamicSharedMemorySize, GSMEM_BYTES);
    cudaFuncSetAttribute(mma_gemm<0, true>,
                         cudaFuncAttributePreferredSharedMemoryCarveout, 100);
    cudaFuncSetAttribute(mma_gemm<1, false>,
                         cudaFuncAttributeMaxDynamicSharedMemorySize, GSMEM_BYTES);
    cudaFuncSetAttribute(mma_gemm<1, false>,
                         cudaFuncAttributePreferredSharedMemoryCarveout, 100);
    cudaFuncSetAttribute(mma_gemm<2, true>,
                         cudaFuncAttributeMaxDynamicSharedMemorySize, GSMEM_BYTES);
    cudaFuncSetAttribute(mma_gemm<2, true>,
                         cudaFuncAttributePreferredSharedMemoryCarveout, 100);

    // 0) round + pack weights
    merge_qkv_kernel<<<(1024*768 + 255)/256, 256>>>(wq, wkv, wqkv_r);
    round4_kernel<<<(DD*DD/4 + 255)/256, 256>>>(wo, wo_r, DD*DD/4);
    round4_kernel<<<(DD*FFF/4 + 255)/256, 256>>>(w1, w1_r, DD*FFF/4);
    round4_kernel<<<(FFF*DD/4 + 255)/256, 256>>>(w2, w2_r, FFF*DD/4);
    // 1) LN1 (rounded output)
    ln_kernel<<<RR, 256>>>(x, ln1g, ln1b, hp);
    // 2) QKV = h @ [wq|wkv]  (4096 x 3072 x 1024, rounded out)
    mma_gemm<0, true><<<dim3(D3/128, RR/128), 256, GSMEM_BYTES>>>(
        hp, DD, wqkv_r, D3, qkvp, D3, DD, nullptr, nullptr, 0);
    // 3) fused attention
    fused_attn<<<dim3(SS/64, BB*NHH), 512, attn_smem>>>(qkvp, Pp, rsp, aop);
    // 4) attn output (b,n,m,h), normalized
    attn_transpose<<<dim3(SS/128, SS, BB), 256>>>(Pp, rsp, out_attn);
    // 5) x2 = x + O @ wo + bo
    mma_gemm<1, false><<<dim3(DD/128, RR/128), 256, GSMEM_BYTES>>>(
        aop, DD, wo_r, DD, x2p, DD, DD, bo, x, DD);
    // 6) LN2 (rounded output)
    ln_kernel<<<RR, 256>>>(x2p, ln2g, ln2b, h2p);
    // 7) FF1 = relu(h2 @ w1 + b1) (rounded out)
    mma_gemm<2, true><<<dim3(FFF/128, RR/128), 256, GSMEM_BYTES>>>(
        h2p, DD, w1_r, FFF, ffp, FFF, DD, b1, nullptr, 0);
    // 8) out = x2 + FF1 @ w2 + b2
    mma_gemm<1, false><<<dim3(DD/128, RR/128), 256, GSMEM_BYTES>>>(
        ffp, FFF, w2_r, DD, out, DD, FFF, b2, x2p, DD);
}

// round 10
// speedup vs baseline: 1.0055x; 1.0055x over previous
#include <cuda_runtime.h>
#include <math.h>
#include <stdint.h>

#define BB 2
#define SS 2048
#define DD 1024
#define NHH 16
#define HDD 64
#define FFF 4096
#define RR (BB*SS)   // 4096 rows
#define D3 (3*DD)    // merged qkv width

// ---------------- scratch ---------------------------------------------------------
__device__ float g_h  [RR*DD];                      // LN1 out / LN2 out
__device__ float g_qkv[(size_t)RR*D3];              // Q|K|V   / x2 (reused)
__device__ float g_ao [RR*DD];                      // attn output (b,s,(h,d))
__device__ float g_ff [(size_t)RR*FFF];             // FFN hidden
__device__ float g_P  [(size_t)BB*NHH*SS*SS];       // unnormalized exp(scores) (b,h,n,m)
__device__ float g_rs [(size_t)BB*NHH*SS];          // softmax row sums
__device__ float g_wr [12*1024*1024];               // tf32-rounded weights

// ---------------- helpers ---------------------------------------------------------
__device__ __forceinline__ void cpa16(void* dst, const void* src) {
    uint32_t d = (uint32_t)__cvta_generic_to_shared(dst);
    asm volatile("cp.async.ca.shared.global [%0], [%1], 16;" :: "r"(d), "l"(src));
}
__device__ __forceinline__ void cp_commit() { asm volatile("cp.async.commit_group;"); }
template<int N> __device__ __forceinline__ void cp_wait() {
    asm volatile("cp.async.wait_group %0;" :: "n"(N));
}
__device__ __forceinline__ float f2tf(float x) {
    uint32_t r;
    asm("cvt.rna.tf32.f32 %0, %1;" : "=r"(r) : "f"(x));
    return __uint_as_float(r);
}
__device__ __forceinline__ void mma8(float* c, const uint32_t* a, const uint32_t* b) {
    asm volatile(
        "mma.sync.aligned.m16n8k8.row.col.f32.tf32.tf32.f32 "
        "{%0,%1,%2,%3},{%4,%5,%6,%7},{%8,%9},{%0,%1,%2,%3};"
        : "+f"(c[0]), "+f"(c[1]), "+f"(c[2]), "+f"(c[3])
        : "r"(a[0]), "r"(a[1]), "r"(a[2]), "r"(a[3]), "r"(b[0]), "r"(b[1]));
}
__device__ __forceinline__ void ldsm4(uint32_t* r, uint32_t a) {
    asm volatile("ldmatrix.sync.aligned.m8n8.x4.shared.b16 {%0,%1,%2,%3}, [%4];"
        : "=r"(r[0]), "=r"(r[1]), "=r"(r[2]), "=r"(r[3]) : "r"(a));
}

// ---------------- prep: round weights, merge wq|wkv -------------------------------
__global__ void __launch_bounds__(256)
round4_kernel(const float* __restrict__ in, float* __restrict__ out, int n4)
{
    int i = blockIdx.x * 256 + threadIdx.x;
    if (i < n4) {
        float4 v = ((const float4*)in)[i];
        v.x = f2tf(v.x); v.y = f2tf(v.y); v.z = f2tf(v.z); v.w = f2tf(v.w);
        ((float4*)out)[i] = v;
    }
}
// merged qkv weights: out[r][0:1024]=wq[r], out[r][1024:3072]=wkv[r]  (rounded)
__global__ void __launch_bounds__(256)
merge_qkv_kernel(const float* __restrict__ wq, const float* __restrict__ wkv,
                 float* __restrict__ out)
{
    int i = blockIdx.x * 256 + threadIdx.x;      // over 1024*768 float4s
    int row = i / 768, c4 = i % 768;
    float4 v;
    if (c4 < 256) v = ((const float4*)wq)[row*256 + c4];
    else          v = ((const float4*)wkv)[row*512 + (c4 - 256)];
    v.x = f2tf(v.x); v.y = f2tf(v.y); v.z = f2tf(v.z); v.w = f2tf(v.w);
    ((float4*)out)[i] = v;
}

// ---------------- dense tf32 GEMM: 128x128, BK=32, 3-stage, ldmatrix A ------------
#define GSTG 8960              // u32 per stage (4608 A + 4352 B)
#define GSMEM_BYTES (3*GSTG*4)
template<int MODE, bool ROUND>
__global__ void __launch_bounds__(256, 2)
mma_gemm(const float* __restrict__ A, int lda,
         const float* __restrict__ B, int ldb,
         float* __restrict__ C, int ldc, int K,
         const float* __restrict__ bias,
         const float* __restrict__ res, int ldr)
{
    extern __shared__ uint32_t smu[];
    float* smf = (float*)smu;

    int tid = threadIdx.x, lane = tid & 31, w = tid >> 5;
    int wm = (w & 1) * 64, wn = (w >> 1) * 32;
    int row0 = blockIdx.y * 128, col0 = blockIdx.x * 128;

    int i8 = lane & 7, j8 = lane >> 3;
    uint32_t abase = (uint32_t)__cvta_generic_to_shared(smu);
    uint32_t aoff[4];
#pragma unroll
    for (int mi = 0; mi < 4; mi++)
        aoff[mi] = ((wm + mi*16 + i8 + (j8 & 1)*8)*36 + (j8 >> 1)*4) * 4;

    float acc[4][4][4];
#pragma unroll
    for (int i = 0; i < 4; i++)
#pragma unroll
        for (int j = 0; j < 4; j++)
#pragma unroll
            for (int l = 0; l < 4; l++) acc[i][j][l] = 0.f;

    int niter = K / 32;

    auto load_blk = [&](int s, int k0) {
        float* As = smf + s*GSTG;
        float* Bs = smf + s*GSTG + 4608;
#pragma unroll
        for (int i = 0; i < 4; i++) {
            int idx = tid + i*256;
            int m = idx >> 3, k4 = (idx & 7) * 4;
            cpa16(&As[m*36 + k4], A + (size_t)(row0 + m)*lda + k0 + k4);
        }
#pragma unroll
        for (int i = 0; i < 4; i++) {
            int idx = tid + i*256;
            int k = idx >> 5, c4 = (idx & 31) * 4;
            cpa16(&Bs[k*136 + c4], B + (size_t)(k0 + k)*ldb + col0 + c4);
        }
        cp_commit();
    };

    load_blk(0, 0);
    load_blk(1, 32);

    for (int it = 0; it < niter; it++) {
        cp_wait<1>();
        __syncthreads();
        if (it + 2 < niter) load_blk((it + 2) % 3, (it + 2) * 32);

        int s = it % 3;
        const uint32_t* Bb = smu + s*GSTG + 4608;
        uint32_t as_base = abase + s*GSTG*4;
#pragma unroll
        for (int ks = 0; ks < 32; ks += 8) {
            uint32_t af[4][4], bf[4][2];
#pragma unroll
            for (int mi = 0; mi < 4; mi++)
                ldsm4(af[mi], as_base + aoff[mi] + ks*4);
#pragma unroll
            for (int ni = 0; ni < 4; ni++) {
                int n = wn + ni*8 + (lane >> 2), kb = ks + (lane & 3);
                bf[ni][0] = Bb[kb*136 + n];  bf[ni][1] = Bb[(kb+4)*136 + n];
            }
#pragma unroll
            for (int mi = 0; mi < 4; mi++)
#pragma unroll
                for (int ni = 0; ni < 4; ni++)
                    mma8(acc[mi][ni], af[mi], bf[ni]);
        }
    }

#pragma unroll
    for (int mi = 0; mi < 4; mi++) {
#pragma unroll
        for (int ni = 0; ni < 4; ni++) {
            int r = row0 + wm + mi*16 + (lane >> 2);
            int c = col0 + wn + ni*8 + 2*(lane & 3);
#pragma unroll
            for (int half = 0; half < 2; half++) {
                int rr = r + half*8;
                float v0 = acc[mi][ni][half*2 + 0];
                float v1 = acc[mi][ni][half*2 + 1];
                if (MODE == 1) {
                    v0 += bias[c]   + res[(size_t)rr*ldr + c];
                    v1 += bias[c+1] + res[(size_t)rr*ldr + c + 1];
                } else if (MODE == 2) {
                    v0 = fmaxf(v0 + bias[c], 0.f);
                    v1 = fmaxf(v1 + bias[c+1], 0.f);
                }
                if (ROUND) { v0 = f2tf(v0); v1 = f2tf(v1); }
                *(float2*)(C + (size_t)rr*ldc + c) = make_float2(v0, v1);
            }
        }
    }
}

// ---------------- fused attention: reads merged qkv (row stride 3072) -------------
// grid (S/64, B*NH), 512 thr. 32 iters of 64 keys, K/V double buffered.
__global__ void __launch_bounds__(512, 2)
fused_attn(const float* __restrict__ QKV,
           float* __restrict__ Eout, float* __restrict__ rs_g,
           float* __restrict__ Og)
{
    extern __shared__ float sm[];
    float* Qs = sm;                    // [64][68]
    float* Ks = Qs + 64*68;            // [2][64][68]
    float* Vs = Ks + 2*64*68;          // [2][64][72]
    float* Es = Vs + 2*64*72;          // [64][68]
    float* rs = Es + 64*68;            // [64]

    int bh = blockIdx.y, b = bh >> 4, h = bh & 15;
    int n0 = blockIdx.x * 64;
    const float* Qp = QKV + (size_t)b*SS*D3 + h*64;          // cols [0,1024)
    const float* Kp = QKV + (size_t)b*SS*D3 + DD   + h*64;   // cols [1024,2048)
    const float* Vp = QKV + (size_t)b*SS*D3 + 2*DD + h*64;   // cols [2048,3072)
    float* Ep = Eout + (size_t)bh*SS*SS + (size_t)n0*SS;

    int tid = threadIdx.x, lane = tid & 31, w = tid >> 5;
    int wy = w & 1, wx = w >> 1;       // wy: 32-row half of 64; wx: 8-col group of 64

    int i8 = lane & 7, j8 = lane >> 3;
    uint32_t qbase = (uint32_t)__cvta_generic_to_shared(Qs);
    uint32_t ebase = (uint32_t)__cvta_generic_to_shared(Es);
    uint32_t moff[2];
#pragma unroll
    for (int mi = 0; mi < 2; mi++)
        moff[mi] = ((wy*32 + mi*16 + i8 + (j8 & 1)*8)*68 + (j8 >> 1)*4) * 4;

    if (tid < 64) rs[tid] = 0.f;

#pragma unroll
    for (int i = 0; i < 2; i++) {
        int idx = tid + i*512; int r = idx >> 4, c4 = (idx & 15) * 4;
        cpa16(&Qs[r*68 + c4], Qp + (size_t)(n0 + r)*D3 + c4);
        cpa16(&Ks[r*68 + c4], Kp + (size_t)r*D3 + c4);
        cpa16(&Vs[r*72 + c4], Vp + (size_t)r*D3 + c4);
    }
    cp_commit();
#pragma unroll
    for (int i = 0; i < 2; i++) {
        int idx = tid + i*512; int r = idx >> 4, c4 = (idx & 15) * 4;
        cpa16(&Ks[64*68 + r*68 + c4], Kp + (size_t)(64 + r)*D3 + c4);
        cpa16(&Vs[64*72 + r*72 + c4], Vp + (size_t)(64 + r)*D3 + c4);
    }
    cp_commit();

    float acc_o[2][4];
    float psum[2][2];
#pragma unroll
    for (int i = 0; i < 2; i++) {
        psum[i][0] = psum[i][1] = 0.f;
#pragma unroll
        for (int l = 0; l < 4; l++) acc_o[i][l] = 0.f;
    }

    for (int it = 0; it < 32; it++) {
        int buf = it & 1;
        int m0 = it * 64;
        if (it + 1 < 32) cp_wait<1>(); else cp_wait<0>();
        __syncthreads();
        const uint32_t* Kb = (const uint32_t*)(Ks + buf*64*68);
        const uint32_t* Vb = (const uint32_t*)(Vs + buf*64*72);

        // ---- S = Q K^T : 64(n) x 64(m), k=64 ----
        float acc_s[2][4];
#pragma unroll
        for (int i = 0; i < 2; i++)
#pragma unroll
            for (int l = 0; l < 4; l++) acc_s[i][l] = 0.f;
#pragma unroll
        for (int ks = 0; ks < 64; ks += 8) {
            uint32_t af[2][4], bf[2];
            ldsm4(af[0], qbase + moff[0] + ks*4);
            ldsm4(af[1], qbase + moff[1] + ks*4);
            {
                int m = wx*8 + (lane >> 2), kk = ks + (lane & 3);
                bf[0] = Kb[m*68 + kk];  bf[1] = Kb[m*68 + kk + 4];
            }
            mma8(acc_s[0], af[0], bf);
            mma8(acc_s[1], af[1], bf);
        }

        // ---- E = round(exp(S/8)); per-thread rowsum; store to Es ----
#pragma unroll
        for (int mi = 0; mi < 2; mi++) {
            int r = wy*32 + mi*16 + (lane >> 2);
            int m = wx*8 + 2*(lane & 3);
            float e0 = f2tf(__expf(acc_s[mi][0] * 0.125f));
            float e1 = f2tf(__expf(acc_s[mi][1] * 0.125f));
            float e2 = f2tf(__expf(acc_s[mi][2] * 0.125f));
            float e3 = f2tf(__expf(acc_s[mi][3] * 0.125f));
            *(float2*)&Es[r*68 + m]     = make_float2(e0, e1);
            *(float2*)&Es[(r+8)*68 + m] = make_float2(e2, e3);
            psum[mi][0] += e0 + e1;
            psum[mi][1] += e2 + e3;
        }
        __syncthreads();

        // ---- coalesced E tile write (64 x 64) ----
        {
            int r = tid >> 3, q = (tid & 7) * 2;
            const float4* src = (const float4*)&Es[r*68];
            float4* dst = (float4*)(Ep + (size_t)r*SS + m0);
            dst[q] = src[q]; dst[q + 1] = src[q + 1];
        }

        // ---- O += E V : 64(n) x 64(d), k=64 ----
#pragma unroll
        for (int ks = 0; ks < 64; ks += 8) {
            uint32_t af[2][4], bf[2];
            ldsm4(af[0], ebase + moff[0] + ks*4);
            ldsm4(af[1], ebase + moff[1] + ks*4);
            {
                int d = wx*8 + (lane >> 2), kk = ks + (lane & 3);
                bf[0] = Vb[kk*72 + d];  bf[1] = Vb[(kk+4)*72 + d];
            }
            mma8(acc_o[0], af[0], bf);
            mma8(acc_o[1], af[1], bf);
        }
        __syncthreads();

        // ---- prefetch K/V tile it+2 into buf ----
        if (it + 2 < 32) {
            int mn = (it + 2) * 64;
#pragma unroll
            for (int i = 0; i < 2; i++) {
                int idx = tid + i*512; int r = idx >> 4, c4 = (idx & 15) * 4;
                cpa16(&Ks[buf*64*68 + r*68 + c4], Kp + (size_t)(mn + r)*D3 + c4);
                cpa16(&Vs[buf*64*72 + r*72 + c4], Vp + (size_t)(mn + r)*D3 + c4);
            }
            cp_commit();
        }
    }

    // ---- rowsum reduction (once) ----
#pragma unroll
    for (int mi = 0; mi < 2; mi++) {
        int r = wy*32 + mi*16 + (lane >> 2);
        float p0 = psum[mi][0], p1 = psum[mi][1];
        p0 += __shfl_xor_sync(0xffffffffu, p0, 1);
        p0 += __shfl_xor_sync(0xffffffffu, p0, 2);
        p1 += __shfl_xor_sync(0xffffffffu, p1, 1);
        p1 += __shfl_xor_sync(0xffffffffu, p1, 2);
        if ((lane & 3) == 0) { atomicAdd(&rs[r], p0); atomicAdd(&rs[r+8], p1); }
    }
    __syncthreads();

    if (tid < 64) rs_g[(size_t)bh*SS + n0 + tid] = rs[tid];
    float* Op = Og + (size_t)b*SS*DD + h*64;
#pragma unroll
    for (int mi = 0; mi < 2; mi++) {
        int r = wy*32 + mi*16 + (lane >> 2);
        int d = wx*8 + 2*(lane & 3);
        float inv0 = 1.f / rs[r], inv1 = 1.f / rs[r+8];
        *(float2*)(Op + (size_t)(n0 + r)*DD + d) =
            make_float2(f2tf(acc_o[mi][0]*inv0), f2tf(acc_o[mi][1]*inv0));
        *(float2*)(Op + (size_t)(n0 + r + 8)*DD + d) =
            make_float2(f2tf(acc_o[mi][2]*inv1), f2tf(acc_o[mi][3]*inv1));
    }
}

// ---------------- LayerNorm (tf32-rounded output) ---------------------------------
__global__ void __launch_bounds__(256)
ln_kernel(const float* __restrict__ x, const float* __restrict__ g,
          const float* __restrict__ beta, float* __restrict__ out)
{
    __shared__ float red[64];
    int row = blockIdx.x;
    const float* xr = x + (size_t)row*DD;
    float* orow = out + (size_t)row*DD;
    int t = threadIdx.x;
    float v[4]; float s = 0.f, sq = 0.f;
#pragma unroll
    for (int i = 0; i < 4; i++) {
        v[i] = xr[t + i*256];
        s += v[i];
        sq = fmaf(v[i], v[i], sq);
    }
#pragma unroll
    for (int o = 16; o > 0; o >>= 1) {
        s  += __shfl_down_sync(0xffffffffu, s,  o);
        sq += __shfl_down_sync(0xffffffffu, sq, o);
    }
    int lane = t & 31, w = t >> 5;
    if (lane == 0) { red[w] = s; red[w + 32] = sq; }
    __syncthreads();
    if (t == 0) {
        float ts = 0.f, tq = 0.f;
        for (int i = 0; i < 8; i++) { ts += red[i]; tq += red[i + 32]; }
        float mu  = ts * (1.0f / DD);
        float var = tq * (1.0f / DD) - mu * mu;
        red[0] = mu;
        red[1] = rsqrtf(var + 1e-5f);
    }
    __syncthreads();
    float mu = red[0], r = red[1];
#pragma unroll
    for (int i = 0; i < 4; i++) {
        int c = t + i*256;
        orow[c] = f2tf((v[i] - mu) * r * g[c] + beta[c]);
    }
}

// ---------------- Transpose+normalize: E(b,h,n,m)/rowsum -> attn(b,n,m,h) --------
__global__ void __launch_bounds__(256)
attn_transpose(const float* __restrict__ P, const float* __restrict__ rs_g,
               float* __restrict__ outA)
{
    __shared__ float tbuf[16][130];
    __shared__ float invs[16];
    int m0 = blockIdx.x * 128;
    int n  = blockIdx.y;
    int b  = blockIdx.z;
    int t  = threadIdx.x;
    if (t < 16) invs[t] = 1.f / rs_g[((size_t)(b*NHH + t))*SS + n];
#pragma unroll
    for (int i = 0; i < 8; i++) {
        int idx = t + i*256;
        int h = idx >> 7, m = idx & 127;
        tbuf[h][m] = P[(((size_t)(b*NHH + h))*SS + n)*SS + m0 + m];
    }
    __syncthreads();
    float* op = outA + (((size_t)b*SS + n)*SS + m0) * NHH;
#pragma unroll
    for (int i = 0; i < 8; i++) {
        int idx = t + i*256;          // idx = m*16 + h
        int m = idx >> 4, h = idx & 15;
        op[idx] = tbuf[h][m] * invs[h];
    }
}

// ---------------- launcher -------------------------------------------------------
extern "C" void kernel_launch(void* const* d_in, const int* in_sizes, int n_in,
                              void* d_out, int out_size)
{
    const float* x    = (const float*)d_in[0];
    const float* ln1g = (const float*)d_in[1];
    const float* ln1b = (const float*)d_in[2];
    const float* wq   = (const float*)d_in[3];
    const float* wkv  = (const float*)d_in[4];
    const float* wo   = (const float*)d_in[5];
    const float* bo   = (const float*)d_in[6];
    const float* ln2g = (const float*)d_in[7];
    const float* ln2b = (const float*)d_in[8];
    const float* w1   = (const float*)d_in[9];
    const float* b1   = (const float*)d_in[10];
    const float* w2   = (const float*)d_in[11];
    const float* b2   = (const float*)d_in[12];

    float* out = (float*)d_out;
    size_t attn_elems = (size_t)BB * SS * SS * NHH;
    float* out_attn = out + ((size_t)out_size - attn_elems);

    float *hp, *qkvp, *aop, *ffp, *Pp, *rsp, *wrp;
    cudaGetSymbolAddress((void**)&hp,   g_h);
    cudaGetSymbolAddress((void**)&qkvp, g_qkv);
    cudaGetSymbolAddress((void**)&aop,  g_ao);
    cudaGetSymbolAddress((void**)&ffp,  g_ff);
    cudaGetSymbolAddress((void**)&Pp,   g_P);
    cudaGetSymbolAddress((void**)&rsp,  g_rs);
    cudaGetSymbolAddress((void**)&wrp,  g_wr);
    float* x2p = qkvp;  // reuse: qkv dead after fused_attn
    float* h2p = hp;    // reuse: LN1 out dead after qkv gemm

    float* wqkv_r = wrp;                 // 3M floats [1024][3072]
    float* wo_r   = wrp + 3*1024*1024;   // 1M
    float* w1_r   = wrp + 4*1024*1024;   // 4M
    float* w2_r   = wrp + 8*1024*1024;   // 4M

    int attn_smem = (64*68 + 2*64*68 + 2*64*72 + 64*68 + 64) * 4;   // 106752 B
    cudaFuncSetAttribute(fused_attn, cudaFuncAttributeMaxDynamicSharedMemorySize,
                         attn_smem);
    cudaFuncSetAttribute(fused_attn, cudaFuncAttributePreferredSharedMemoryCarveout, 100);
    cudaFuncSetAttribute(mma_gemm<0, true>,
                         cudaFuncAttributeMaxDynamicSharedMemorySize, GSMEM_BYTES);
    cudaFuncSetAttribute(mma_gemm<0, true>,
                         cudaFuncAttributePreferredSharedMemoryCarveout, 100);
    cudaFuncSetAttribute(mma_gemm<1, false>,
                         cudaFuncAttributeMaxDynamicSharedMemorySize, GSMEM_BYTES);
    cudaFuncSetAttribute(mma_gemm<1, false>,
                         cudaFuncAttributePreferredSharedMemoryCarveout, 100);
    cudaFuncSetAttribute(mma_gemm<2, true>,
                         cudaFuncAttributeMaxDynamicSharedMemorySize, GSMEM_BYTES);
    cudaFuncSetAttribute(mma_gemm<2, true>,
                         cudaFuncAttributePreferredSharedMemoryCarveout, 100);

    // 0) round + pack weights
    merge_qkv_kernel<<<(1024*768 + 255)/256, 256>>>(wq, wkv, wqkv_r);
    round4_kernel<<<(DD*DD/4 + 255)/256, 256>>>(wo, wo_r, DD*DD/4);
    round4_kernel<<<(DD*FFF/4 + 255)/256, 256>>>(w1, w1_r, DD*FFF/4);
    round4_kernel<<<(FFF*DD/4 + 255)/256, 256>>>(w2, w2_r, FFF*DD/4);
    // 1) LN1 (rounded output)
    ln_kernel<<<RR, 256>>>(x, ln1g, ln1b, hp);
    // 2) QKV = h @ [wq|wkv]  (4096 x 3072 x 1024, rounded out)
    mma_gemm<0, true><<<dim3(D3/128, RR/128), 256, GSMEM_BYTES>>>(
        hp, DD, wqkv_r, D3, qkvp, D3, DD, nullptr, nullptr, 0);
    // 3) fused attention
    fused_attn<<<dim3(SS/64, BB*NHH), 512, attn_smem>>>(qkvp, Pp, rsp, aop);
    // 4) attn output (b,n,m,h), normalized
    attn_transpose<<<dim3(SS/128, SS, BB), 256>>>(Pp, rsp, out_attn);
    // 5) x2 = x + O @ wo + bo
    mma_gemm<1, false><<<dim3(DD/128, RR/128), 256, GSMEM_BYTES>>>(
        aop, DD, wo_r, DD, x2p, DD, DD, bo, x, DD);
    // 6) LN2 (rounded output)
    ln_kernel<<<RR, 256>>>(x2p, ln2g, ln2b, h2p);
    // 7) FF1 = relu(h2 @ w1 + b1) (rounded out)
    mma_gemm<2, true><<<dim3(FFF/128, RR/128), 256, GSMEM_BYTES>>>(
        h2p, DD, w1_r, FFF, ffp, FFF, DD, b1, nullptr, 0);
    // 8) out = x2 + FF1 @ w2 + b2
    mma_gemm<1, false><<<dim3(DD/128, RR/128), 256, GSMEM_BYTES>>>(
        ffp, FFF, w2_r, DD, out, DD, FFF, b2, x2p, DD);
}

// round 15
// speedup vs baseline: 1.0623x; 1.0565x over previous
#include <cuda_runtime.h>
#include <math.h>
#include <stdint.h>

#define BB 2
#define SS 2048
#define DD 1024
#define NHH 16
#define FFF 4096
#define RR (BB*SS)

__device__ float g_h [RR*DD];
__device__ float g_q [RR*DD];
__device__ float g_kv[RR*2*DD];
__device__ float g_ao[RR*DD];
__device__ float g_ff[(size_t)RR*FFF];
__device__ float g_P [(size_t)BB*NHH*SS*SS];
__device__ float g_rs[(size_t)BB*NHH*SS];
__device__ float g_wr[12*1024*1024];

__device__ __forceinline__ void cpa16(void* dst, const void* src) {
    uint32_t d = (uint32_t)__cvta_generic_to_shared(dst);
    asm volatile("cp.async.ca.shared.global [%0], [%1], 16;" :: "r"(d), "l"(src));
}
__device__ __forceinline__ void cp_commit() { asm volatile("cp.async.commit_group;"); }
template<int N> __device__ __forceinline__ void cp_wait() {
    asm volatile("cp.async.wait_group %0;" :: "n"(N));
}
__device__ __forceinline__ float f2tf(float x) {
    uint32_t r; asm("cvt.rna.tf32.f32 %0, %1;" : "=r"(r) : "f"(x));
    return __uint_as_float(r);
}
__device__ __forceinline__ void mma8(float* c, const uint32_t* a, const uint32_t* b) {
    asm volatile("mma.sync.aligned.m16n8k8.row.col.f32.tf32.tf32.f32 "
        "{%0,%1,%2,%3},{%4,%5,%6,%7},{%8,%9},{%0,%1,%2,%3};"
        : "+f"(c[0]), "+f"(c[1]), "+f"(c[2]), "+f"(c[3])
        : "r"(a[0]), "r"(a[1]), "r"(a[2]), "r"(a[3]), "r"(b[0]), "r"(b[1]));
}
__device__ __forceinline__ void ldsm4(uint32_t* r, uint32_t a) {
    asm volatile("ldmatrix.sync.aligned.m8n8.x4.shared.b16 {%0,%1,%2,%3}, [%4];"
        : "=r"(r[0]), "=r"(r[1]), "=r"(r[2]), "=r"(r[3]) : "r"(a));
}

__global__ void __launch_bounds__(256)
round4_kernel(const float* __restrict__ in, float* __restrict__ out, int n4)
{
    int i = blockIdx.x * 256 + threadIdx.x;
    if (i < n4) {
        float4 v = ((const float4*)in)[i];
        v.x = f2tf(v.x); v.y = f2tf(v.y); v.z = f2tf(v.z); v.w = f2tf(v.w);
        ((float4*)out)[i] = v;
    }
}

// ---- dense tf32 GEMM (unchanged from R8 best) ----
#define GSTG 8960
#define GSMEM_BYTES (3*GSTG*4)
template<int MODE, bool ROUND>
__global__ void __launch_bounds__(256, 2)
mma_gemm(const float* __restrict__ A, int lda,
         const float* __restrict__ B, int ldb,
         float* __restrict__ C, int ldc, int K,
         const float* __restrict__ bias,
         const float* __restrict__ res, int ldr)
{
    extern __shared__ uint32_t smu[];
    float* smf = (float*)smu;
    int tid = threadIdx.x, lane = tid & 31, w = tid >> 5;
    int wm = (w & 1) * 64, wn = (w >> 1) * 32;
    int row0 = blockIdx.y * 128, col0 = blockIdx.x * 128;

    int i8 = lane & 7, j8 = lane >> 3;
    uint32_t abase = (uint32_t)__cvta_generic_to_shared(smu);
    uint32_t aoff[4];
#pragma unroll
    for (int mi = 0; mi < 4; mi++)
        aoff[mi] = ((wm + mi*16 + i8 + (j8 & 1)*8)*36 + (j8 >> 1)*4) * 4;

    float acc[4][4][4];
#pragma unroll
    for (int i = 0; i < 4; i++)
#pragma unroll
        for (int j = 0; j < 4; j++)
#pragma unroll
            for (int l = 0; l < 4; l++) acc[i][j][l] = 0.f;

    int niter = K / 32;
    auto load_blk = [&](int s, int k0) {
        float* As = smf + s*GSTG;
        float* Bs = smf + s*GSTG + 4608;
#pragma unroll
        for (int i = 0; i < 4; i++) {
            int idx = tid + i*256;
            int m = idx >> 3, k4 = (idx & 7) * 4;
            cpa16(&As[m*36 + k4], A + (size_t)(row0 + m)*lda + k0 + k4);
        }
#pragma unroll
        for (int i = 0; i < 4; i++) {
            int idx = tid + i*256;
            int k = idx >> 5, c4 = (idx & 31) * 4;
            cpa16(&Bs[k*136 + c4], B + (size_t)(k0 + k)*ldb + col0 + c4);
        }
        cp_commit();
    };

    load_blk(0, 0);
    load_blk(1, 32);

    for (int it = 0; it < niter; it++) {
        cp_wait<1>();
        __syncthreads();
        if (it + 2 < niter) load_blk((it + 2) % 3, (it + 2) * 32);
        int s = it % 3;
        const uint32_t* Bb = smu + s*GSTG + 4608;
        uint32_t as_base = abase + s*GSTG*4;
#pragma unroll
        for (int ks = 0; ks < 32; ks += 8) {
            uint32_t af[4][4], bf[4][2];
#pragma unroll
            for (int mi = 0; mi < 4; mi++)
                ldsm4(af[mi], as_base + aoff[mi] + ks*4);
#pragma unroll
            for (int ni = 0; ni < 4; ni++) {
                int n = wn + ni*8 + (lane >> 2), kb = ks + (lane & 3);
                bf[ni][0] = Bb[kb*136 + n];  bf[ni][1] = Bb[(kb+4)*136 + n];
            }
#pragma unroll
            for (int mi = 0; mi < 4; mi++)
#pragma unroll
                for (int ni = 0; ni < 4; ni++)
                    mma8(acc[mi][ni], af[mi], bf[ni]);
        }
    }

#pragma unroll
    for (int mi = 0; mi < 4; mi++) {
#pragma unroll
        for (int ni = 0; ni < 4; ni++) {
            int r = row0 + wm + mi*16 + (lane >> 2);
            int c = col0 + wn + ni*8 + 2*(lane & 3);
#pragma unroll
            for (int half = 0; half < 2; half++) {
                int rr = r + half*8;
                float v0 = acc[mi][ni][half*2 + 0];
                float v1 = acc[mi][ni][half*2 + 1];
                if (MODE == 1) {
                    v0 += bias[c]   + res[(size_t)rr*ldr + c];
                    v1 += bias[c+1] + res[(size_t)rr*ldr + c + 1];
                } else if (MODE == 2) {
                    v0 = fmaxf(v0 + bias[c], 0.f);
                    v1 = fmaxf(v1 + bias[c+1], 0.f);
                }
                if (ROUND) { v0 = f2tf(v0); v1 = f2tf(v1); }
                *(float2*)(C + (size_t)rr*ldc + c) = make_float2(v0, v1);
            }
        }
    }
}

// ---- fused attention v5: 256 thr, 8 warps, 32x16 warp tiles, ldmatrix K ----
__global__ void __launch_bounds__(256, 2)
fused_attn(const float* __restrict__ Q, const float* __restrict__ KV,
           float* __restrict__ Eout, float* __restrict__ rs_g,
           float* __restrict__ Og)
{
    extern __shared__ float sm[];
    float* Qs = sm;                    // [64][68]
    float* Ks = Qs + 64*68;            // [2][64][68]
    float* Vs = Ks + 2*64*68;          // [2][64][72]
    float* Es = Vs + 2*64*72;          // [64][68]
    float* rs = Es + 64*68;            // [64]

    int bh = blockIdx.y, b = bh >> 4, h = bh & 15;
    int n0 = blockIdx.x * 64;
    const float* Qp = Q  + (size_t)b*SS*DD     + h*64;
    const float* Kp = KV + (size_t)b*SS*(2*DD) + h*64;
    const float* Vp = Kp + DD;
    float* Ep = Eout + (size_t)bh*SS*SS + (size_t)n0*SS;

    int tid = threadIdx.x, lane = tid & 31, w = tid >> 5;
    int wm = (w & 1) * 32, wn = (w >> 1) * 16;
    int i8 = lane & 7, j8 = lane >> 3;
    uint32_t qbase = (uint32_t)__cvta_generic_to_shared(Qs);
    uint32_t ebase = (uint32_t)__cvta_generic_to_shared(Es);
    uint32_t kbase = (uint32_t)__cvta_generic_to_shared(Ks);
    uint32_t moff[2];
#pragma unroll
    for (int mi = 0; mi < 2; mi++)
        moff[mi] = ((wm + mi*16 + i8 + (j8 & 1)*8)*68 + (j8 >> 1)*4) * 4;
    uint32_t koff = ((wn + i8 + (j8 & 1)*8)*68 + (j8 >> 1)*4) * 4;

    if (tid < 64) rs[tid] = 0.f;

    // prologue: Q + K/V tile 0; then K/V tile 1
#pragma unroll
    for (int i = 0; i < 4; i++) {
        int idx = tid + i*256; int r = idx >> 4, c4 = (idx & 15) * 4;
        cpa16(&Qs[r*68 + c4], Qp + (size_t)(n0 + r)*DD + c4);
        cpa16(&Ks[r*68 + c4], Kp + (size_t)r*(2*DD) + c4);
        cpa16(&Vs[r*72 + c4], Vp + (size_t)r*(2*DD) + c4);
    }
    cp_commit();
#pragma unroll
    for (int i = 0; i < 4; i++) {
        int idx = tid + i*256; int r = idx >> 4, c4 = (idx & 15) * 4;
        cpa16(&Ks[64*68 + r*68 + c4], Kp + (size_t)(64 + r)*(2*DD) + c4);
        cpa16(&Vs[64*72 + r*72 + c4], Vp + (size_t)(64 + r)*(2*DD) + c4);
    }
    cp_commit();

    float acc_o[2][2][4];
    float psum[2][2];
#pragma unroll
    for (int i = 0; i < 2; i++) {
        psum[i][0] = psum[i][1] = 0.f;
#pragma unroll
        for (int j = 0; j < 2; j++)
#pragma unroll
            for (int l = 0; l < 4; l++) acc_o[i][j][l] = 0.f;
    }

    for (int it = 0; it < 32; it++) {
        int buf = it & 1;
        int m0 = it * 64;
        if (it + 1 < 32) cp_wait<1>(); else cp_wait<0>();
        __syncthreads();
        uint32_t kb_b = kbase + (uint32_t)buf*64*68*4;
        const uint32_t* Vb = (const uint32_t*)(Vs + buf*64*72);

        // ---- S = Q K^T : 64x64, k=64; per ks: 3 ldsm4 + 4 mma ----
        float acc_s[2][2][4];
#pragma unroll
        for (int i = 0; i < 2; i++)
#pragma unroll
            for (int j = 0; j < 2; j++)
#pragma unroll
                for (int l = 0; l < 4; l++) acc_s[i][j][l] = 0.f;
#pragma unroll
        for (int ks = 0; ks < 64; ks += 8) {
            uint32_t aq0[4], aq1[4], bk[4];
            ldsm4(aq0, qbase + moff[0] + ks*4);
            ldsm4(aq1, qbase + moff[1] + ks*4);
            ldsm4(bk, kb_b + koff + ks*4);
            uint32_t bf0[2] = {bk[0], bk[2]};
            uint32_t bf1[2] = {bk[1], bk[3]};
            mma8(acc_s[0][0], aq0, bf0); mma8(acc_s[0][1], aq0, bf1);
            mma8(acc_s[1][0], aq1, bf0); mma8(acc_s[1][1], aq1, bf1);
        }

        // ---- E = round(exp(S/8)); per-thread rowsum; store to Es ----
#pragma unroll
        for (int mi = 0; mi < 2; mi++) {
            int r = wm + mi*16 + (lane >> 2);
#pragma unroll
            for (int ni = 0; ni < 2; ni++) {
                int c = wn + ni*8 + 2*(lane & 3);
                float e0 = f2tf(__expf(acc_s[mi][ni][0] * 0.125f));
                float e1 = f2tf(__expf(acc_s[mi][ni][1] * 0.125f));
                float e2 = f2tf(__expf(acc_s[mi][ni][2] * 0.125f));
                float e3 = f2tf(__expf(acc_s[mi][ni][3] * 0.125f));
                *(float2*)&Es[r*68 + c]     = make_float2(e0, e1);
                *(float2*)&Es[(r+8)*68 + c] = make_float2(e2, e3);
                psum[mi][0] += e0 + e1;
                psum[mi][1] += e2 + e3;
            }
        }
        __syncthreads();

        // ---- coalesced E tile write (64 x 64) ----
        {
            int r = tid >> 2, q = (tid & 3) * 4;
            const float4* src = (const float4*)&Es[r*68];
            float4* dst = (float4*)(Ep + (size_t)r*SS + m0);
#pragma unroll
            for (int j = 0; j < 4; j++) dst[q + j] = src[q + j];
        }

        // ---- O += E V : 64x64, k=64 ----
#pragma unroll
        for (int ks = 0; ks < 64; ks += 8) {
            uint32_t ae0[4], ae1[4], bf[2][2];
            ldsm4(ae0, ebase + moff[0] + ks*4);
            ldsm4(ae1, ebase + moff[1] + ks*4);
#pragma unroll
            for (int ni = 0; ni < 2; ni++) {
                int d = wn + ni*8 + (lane >> 2), kk = ks + (lane & 3);
                bf[ni][0] = Vb[kk*72 + d];  bf[ni][1] = Vb[(kk+4)*72 + d];
            }
            mma8(acc_o[0][0], ae0, bf[0]); mma8(acc_o[0][1], ae0, bf[1]);
            mma8(acc_o[1][0], ae1, bf[0]); mma8(acc_o[1][1], ae1, bf[1]);
        }
        __syncthreads();

        // ---- prefetch K/V tile it+2 ----
        if (it + 2 < 32) {
            int mn = (it + 2) * 64;
#pragma unroll
            for (int i = 0; i < 4; i++) {
                int idx = tid + i*256; int r = idx >> 4, c4 = (idx & 15) * 4;
                cpa16(&Ks[buf*64*68 + r*68 + c4], Kp + (size_t)(mn + r)*(2*DD) + c4);
                cpa16(&Vs[buf*64*72 + r*72 + c4], Vp + (size_t)(mn + r)*(2*DD) + c4);
            }
            cp_commit();
        }
    }

    // ---- rowsum reduction ----
#pragma unroll
    for (int mi = 0; mi < 2; mi++) {
        int r = wm + mi*16 + (lane >> 2);
        float p0 = psum[mi][0], p1 = psum[mi][1];
        p0 += __shfl_xor_sync(0xffffffffu, p0, 1);
        p0 += __shfl_xor_sync(0xffffffffu, p0, 2);
        p1 += __shfl_xor_sync(0xffffffffu, p1, 1);
        p1 += __shfl_xor_sync(0xffffffffu, p1, 2);
        if ((lane & 3) == 0) { atomicAdd(&rs[r], p0); atomicAdd(&rs[r+8], p1); }
    }
    __syncthreads();

    if (tid < 64) rs_g[(size_t)bh*SS + n0 + tid] = rs[tid];
    float* Op = Og + (size_t)b*SS*DD + h*64;
#pragma unroll
    for (int mi = 0; mi < 2; mi++) {
        int r = wm + mi*16 + (lane >> 2);
        float inv0 = 1.f / rs[r], inv1 = 1.f / rs[r+8];
#pragma unroll
        for (int ni = 0; ni < 2; ni++) {
            int d = wn + ni*8 + 2*(lane & 3);
            *(float2*)(Op + (size_t)(n0 + r)*DD + d) =
                make_float2(f2tf(acc_o[mi][ni][0]*inv0), f2tf(acc_o[mi][ni][1]*inv0));
            *(float2*)(Op + (size_t)(n0 + r + 8)*DD + d) =
                make_float2(f2tf(acc_o[mi][ni][2]*inv1), f2tf(acc_o[mi][ni][3]*inv1));
        }
    }
}

// ---- LayerNorm (tf32-rounded output) ----
__global__ void __launch_bounds__(256)
ln_kernel(const float* __restrict__ x, const float* __restrict__ g,
          const float* __restrict__ beta, float* __restrict__ out)
{
    __shared__ float red[64];
    int row = blockIdx.x;
    const float* xr = x + (size_t)row*DD;
    float* orow = out + (size_t)row*DD;
    int t = threadIdx.x;
    float v[4]; float s = 0.f, sq = 0.f;
#pragma unroll
    for (int i = 0; i < 4; i++) {
        v[i] = xr[t + i*256]; s += v[i]; sq = fmaf(v[i], v[i], sq);
    }
#pragma unroll
    for (int o = 16; o > 0; o >>= 1) {
        s  += __shfl_down_sync(0xffffffffu, s,  o);
        sq += __shfl_down_sync(0xffffffffu, sq, o);
    }
    int lane = t & 31, w = t >> 5;
    if (lane == 0) { red[w] = s; red[w + 32] = sq; }
    __syncthreads();
    if (t == 0) {
        float ts = 0.f, tq = 0.f;
        for (int i = 0; i < 8; i++) { ts += red[i]; tq += red[i + 32]; }
        float mu = ts * (1.0f / DD);
        red[0] = mu;
        red[1] = rsqrtf(tq * (1.0f / DD) - mu*mu + 1e-5f);
    }
    __syncthreads();
    float mu = red[0], r = red[1];
#pragma unroll
    for (int i = 0; i < 4; i++) {
        int c = t + i*256;
        orow[c] = f2tf((v[i] - mu) * r * g[c] + beta[c]);
    }
}

// ---- transpose + normalize ----
__global__ void __launch_bounds__(256)
attn_transpose(const float* __restrict__ P, const float* __restrict__ rs_g,
               float* __restrict__ outA)
{
    __shared__ float tbuf[16][130];
    __shared__ float invs[16];
    int m0 = blockIdx.x * 128, n = blockIdx.y, b = blockIdx.z;
    int t = threadIdx.x;
    if (t < 16) invs[t] = 1.f / rs_g[((size_t)(b*NHH + t))*SS + n];
#pragma unroll
    for (int i = 0; i < 8; i++) {
        int idx = t + i*256;
        int h = idx >> 7, m = idx & 127;
        tbuf[h][m] = P[(((size_t)(b*NHH + h))*SS + n)*SS + m0 + m];
    }
    __syncthreads();
    float* op = outA + (((size_t)b*SS + n)*SS + m0) * NHH;
#pragma unroll
    for (int i = 0; i < 8; i++) {
        int idx = t + i*256;
        int m = idx >> 4, h = idx & 15;
        op[idx] = tbuf[h][m] * invs[h];
    }
}

// ---- launcher ----
extern "C" void kernel_launch(void* const* d_in, const int* in_sizes, int n_in,
                              void* d_out, int out_size)
{
    const float* x    = (const float*)d_in[0];
    const float* ln1g = (const float*)d_in[1];
    const float* ln1b = (const float*)d_in[2];
    const float* wq   = (const float*)d_in[3];
    const float* wkv  = (const float*)d_in[4];
    const float* wo   = (const float*)d_in[5];
    const float* bo   = (const float*)d_in[6];
    const float* ln2g = (const float*)d_in[7];
    const float* ln2b = (const float*)d_in[8];
    const float* w1   = (const float*)d_in[9];
    const float* b1   = (const float*)d_in[10];
    const float* w2   = (const float*)d_in[11];
    const float* b2   = (const float*)d_in[12];

    float* out = (float*)d_out;
    size_t attn_elems = (size_t)BB * SS * SS * NHH;
    float* out_attn = out + ((size_t)out_size - attn_elems);

    float *hp, *qp, *kvp, *aop, *ffp, *Pp, *rsp, *wrp;
    cudaGetSymbolAddress((void**)&hp,  g_h);
    cudaGetSymbolAddress((void**)&qp,  g_q);
    cudaGetSymbolAddress((void**)&kvp, g_kv);
    cudaGetSymbolAddress((void**)&aop, g_ao);
    cudaGetSymbolAddress((void**)&ffp, g_ff);
    cudaGetSymbolAddress((void**)&Pp,  g_P);
    cudaGetSymbolAddress((void**)&rsp, g_rs);
    cudaGetSymbolAddress((void**)&wrp, g_wr);
    float* x2p = qp;
    float* h2p = hp;

    float* wq_r  = wrp;
    float* wkv_r = wrp + 1024*1024;
    float* wo_r  = wrp + 3*1024*1024;
    float* w1_r  = wrp + 4*1024*1024;
    float* w2_r  = wrp + 8*1024*1024;

    int attn_smem = (64*68 + 2*64*68 + 2*64*72 + 64*68 + 64) * 4;   // 106752 B
    cudaFuncSetAttribute(fused_attn, cudaFuncAttributeMaxDynamicSharedMemorySize,
                         attn_smem);
    cudaFuncSetAttribute(fused_attn, cudaFuncAttributePreferredSharedMemoryCarveout, 100);
    cudaFuncSetAttribute(mma_gemm<0, true>,
                         cudaFuncAttributeMaxDynamicSharedMemorySize, GSMEM_BYTES);
    cudaFuncSetAttribute(mma_gemm<1, false>,
                         cudaFuncAttributeMaxDynamicSharedMemorySize, GSMEM_BYTES);
    cudaFuncSetAttribute(mma_gemm<2, true>,
                         cudaFuncAttributeMaxDynamicSharedMemorySize, GSMEM_BYTES);

    round4_kernel<<<(DD*DD/4 + 255)/256, 256>>>(wq, wq_r, DD*DD/4);
    round4_kernel<<<(2*DD*DD/4 + 255)/256, 256>>>(wkv, wkv_r, 2*DD*DD/4);
    round4_kernel<<<(DD*DD/4 + 255)/256, 256>>>(wo, wo_r, DD*DD/4);
    round4_kernel<<<(DD*FFF/4 + 255)/256, 256>>>(w1, w1_r, DD*FFF/4);
    round4_kernel<<<(FFF*DD/4 + 255)/256, 256>>>(w2, w2_r, FFF*DD/4);
    ln_kernel<<<RR, 256>>>(x, ln1g, ln1b, hp);
    mma_gemm<0, true><<<dim3(DD/128, RR/128), 256, GSMEM_BYTES>>>(
        hp, DD, wq_r, DD, qp, DD, DD, nullptr, nullptr, 0);
    mma_gemm<0, true><<<dim3(2*DD/128, RR/128), 256, GSMEM_BYTES>>>(
        hp, DD, wkv_r, 2*DD, kvp, 2*DD, DD, nullptr, nullptr, 0);
    fused_attn<<<dim3(SS/64, BB*NHH), 256, attn_smem>>>(qp, kvp, Pp, rsp, aop);
    attn_transpose<<<dim3(SS/128, SS, BB), 256>>>(Pp, rsp, out_attn);
    mma_gemm<1, false><<<dim3(DD/128, RR/128), 256, GSMEM_BYTES>>>(
        aop, DD, wo_r, DD, x2p, DD, DD, bo, x, DD);
    ln_kernel<<<RR, 256>>>(x2p, ln2g, ln2b, h2p);
    mma_gemm<2, true><<<dim3(FFF/128, RR/128), 256, GSMEM_BYTES>>>(
        h2p, DD, w1_r, FFF, ffp, FFF, DD, b1, nullptr, 0);
    mma_gemm<1, false><<<dim3(DD/128, RR/128), 256, GSMEM_BYTES>>>(
        ffp, FFF, w2_r, DD, out, DD, FFF, b2, x2p, DD);
}